// round 9
// baseline (speedup 1.0000x reference)
#include <cuda_runtime.h>
#include <math_constants.h>

#define BN_EPS 1e-3f
#define NPTS 2048
#define NBATCH 8
#define NROWS (NPTS * NBATCH)
#define KNN 16
#define NSPLIT 2

typedef unsigned long long u64;

__device__ float g_xcat[NROWS * 512];
__device__ float g_ytb[NROWS * 512];
__device__ float g_sq[NROWS];
__device__ int   g_idx[NROWS * KNN];
__device__ float g_cv[NROWS * KNN * NSPLIT];
__device__ int   g_ci[NROWS * KNN * NSPLIT];

// ---------------- f32x2 packed helpers (FFMA2: 2x fp32 throughput) ----------
__device__ __forceinline__ void ffma2(u64& d, u64 a, u64 b) {
    asm("fma.rn.f32x2 %0, %1, %2, %0;" : "+l"(d) : "l"(a), "l"(b));
}
__device__ __forceinline__ float2 unpack2(u64 v) {
    float2 r;
    asm("mov.b64 {%0, %1}, %2;" : "=f"(r.x), "=f"(r.y) : "l"(v));
    return r;
}

// ---------------------------------------------------------------------------
__global__ void sqnorm_kernel(const float* __restrict__ x, int lda, int C,
                              float* __restrict__ sq) {
    int i = blockIdx.x * blockDim.x + threadIdx.x;
    if (i < NROWS) {
        const float* p = x + (long long)i * lda;
        float s = 0.f;
        for (int c = 0; c < C; c++) { float v = p[c]; s = fmaf(v, v, s); }
        sq[i] = s;
    }
}

// ---------------------------------------------------------------------------
__device__ __forceinline__ void topk_ins(float (&v)[16], int (&id)[16],
                                         float& vmin, int& vminid, int& minpos,
                                         float pv, int jg) {
    if (pv > vmin || (pv == vmin && jg < vminid)) {
#pragma unroll
        for (int q = 0; q < 16; q++)
            if (q == minpos) { v[q] = pv; id[q] = jg; }
        vmin = v[0]; vminid = id[0]; minpos = 0;
#pragma unroll
        for (int q = 1; q < 16; q++) {
            bool w = (v[q] < vmin) || (v[q] == vmin && id[q] > vminid);
            if (w) { vmin = v[q]; vminid = id[q]; minpos = q; }
        }
    }
}

// ---------------------------------------------------------------------------
// kNN (split): 64 i-rows x (NPTS/NSPLIT) j-range per block, 64-j tiles,
// 256 threads, 4x4 micro-tile in f32x2 (R4-proven loop). pd aliases xjT.
// Selection gated by tile-level and float4-level pre-max vs current vmin
// (strict-less proves no candidate can enter; >= keeps tie-break exactness).
// ---------------------------------------------------------------------------
template <int C>
__global__ void knn_kernel(const float* __restrict__ x, int lda,
                           const float* __restrict__ sq,
                           float* __restrict__ outcv, int* __restrict__ outci) {
    constexpr int BUFROWS = (C > 64) ? C : 64;
    extern __shared__ float sm[];
    float* xiD = sm;                    // C x 136 (dup: (v,v) pairs)
    float* buf = sm + C * 136;          // BUFROWS x 68: xjT then pd (aliased)

    const int rowbase = blockIdx.y * NPTS;
    const int i0 = blockIdx.x * 64;
    const int spbase = blockIdx.z * (NPTS / NSPLIT);
    const int tid = threadIdx.x;
    const int ty = tid >> 4, tx = tid & 15;
    const int srow = tid >> 2, sq4 = tid & 3;

    for (int t = tid; t < 64 * C; t += 256) {
        int i = t / C, c = t - i * C;
        float val = x[(long long)(rowbase + i0 + i) * lda + c];
        xiD[c * 136 + 2 * i] = val;
        xiD[c * 136 + 2 * i + 1] = val;
    }
    float sqi[4];
#pragma unroll
    for (int r = 0; r < 4; r++) sqi[r] = sq[rowbase + i0 + ty * 4 + r];

    float v[16]; int id[16];
#pragma unroll
    for (int q = 0; q < 16; q++) { v[q] = -CUDART_INF_F; id[q] = 0x7fffffff; }
    float vmin = -CUDART_INF_F; int vminid = 0x7fffffff; int minpos = 0;

    const float* xip = xiD + ty * 8;
    const float* xjp = buf + tx * 4;

    for (int jt = 0; jt < NPTS / NSPLIT / 64; jt++) {
        const int j0 = spbase + jt * 64;
        __syncthreads();   // prev selection (pd reads) done
        for (int t = tid; t < 64 * C; t += 256) {
            int j = t / C, c = t - j * C;
            buf[c * 68 + j] = x[(long long)(rowbase + j0 + j) * lda + c];
        }
        __syncthreads();

        u64 acc[4][2];
#pragma unroll
        for (int r = 0; r < 4; r++) { acc[r][0] = 0ull; acc[r][1] = 0ull; }

#pragma unroll 4
        for (int c = 0; c < C; c++) {
            ulonglong2 a01 = *(const ulonglong2*)(xip + c * 136);
            ulonglong2 a23 = *(const ulonglong2*)(xip + c * 136 + 4);
            ulonglong2 bq  = *(const ulonglong2*)(xjp + c * 68);
            ffma2(acc[0][0], a01.x, bq.x); ffma2(acc[0][1], a01.x, bq.y);
            ffma2(acc[1][0], a01.y, bq.x); ffma2(acc[1][1], a01.y, bq.y);
            ffma2(acc[2][0], a23.x, bq.x); ffma2(acc[2][1], a23.x, bq.y);
            ffma2(acc[3][0], a23.y, bq.x); ffma2(acc[3][1], a23.y, bq.y);
        }
        __syncthreads();   // all xjT reads done before pd overwrites buf

        float4 sj = *(const float4*)&sq[rowbase + j0 + tx * 4];
#pragma unroll
        for (int r = 0; r < 4; r++) {
            float2 lo = unpack2(acc[r][0]);
            float2 hi = unpack2(acc[r][1]);
            float4 o;
            o.x = 2.f * lo.x - sqi[r] - sj.x;
            o.y = 2.f * lo.y - sqi[r] - sj.y;
            o.z = 2.f * hi.x - sqi[r] - sj.z;
            o.w = 2.f * hi.y - sqi[r] - sj.w;
            *(float4*)&buf[(ty * 4 + r) * 68 + tx * 4] = o;   // pd
        }
        __syncthreads();

        // selection: thread (srow, sq4) scans j strip [sq4*16, sq4*16+16).
        // tile-level pre-max gate: strict < vmin proves nothing can enter.
        float tmax = -CUDART_INF_F;
#pragma unroll
        for (int s = 0; s < 4; s++) {
            const float4 pv = *(const float4*)&buf[srow * 68 + sq4 * 16 + s * 4];
            tmax = fmaxf(tmax, fmaxf(fmaxf(pv.x, pv.y), fmaxf(pv.z, pv.w)));
        }
        if (tmax >= vmin) {
#pragma unroll
            for (int s = 0; s < 4; s++) {
                const float4 pv = *(const float4*)&buf[srow * 68 + sq4 * 16 + s * 4];
                float m4 = fmaxf(fmaxf(pv.x, pv.y), fmaxf(pv.z, pv.w));
                if (m4 >= vmin) {
                    int jb = j0 + sq4 * 16 + s * 4;
                    topk_ins(v, id, vmin, vminid, minpos, pv.x, jb);
                    topk_ins(v, id, vmin, vminid, minpos, pv.y, jb + 1);
                    topk_ins(v, id, vmin, vminid, minpos, pv.z, jb + 2);
                    topk_ins(v, id, vmin, vminid, minpos, pv.w, jb + 3);
                }
            }
        }
    }

    // merge 4 lanes x 16 entries -> top-16 per row via warp shuffles
    const long long crow = (long long)(rowbase + i0 + srow) * (KNN * NSPLIT)
                           + blockIdx.z * KNN;
    for (int t = 0; t < KNN; t++) {
        float bv = -CUDART_INF_F; int bid = 0x7fffffff; int bq = 0;
#pragma unroll
        for (int q = 0; q < 16; q++) {
            bool w = (v[q] > bv) || (v[q] == bv && id[q] < bid);
            if (w) { bv = v[q]; bid = id[q]; bq = q; }
        }
        float lv = bv; int lid = bid;
#pragma unroll
        for (int off = 1; off < 4; off <<= 1) {
            float ov = __shfl_xor_sync(0xffffffffu, bv, off);
            int oid = __shfl_xor_sync(0xffffffffu, bid, off);
            if (ov > bv || (ov == bv && oid < bid)) { bv = ov; bid = oid; }
        }
        if (lid == bid && lv == bv) { v[bq] = -CUDART_INF_F; id[bq] = 0x7fffffff; }
        if (sq4 == 0) { outcv[crow + t] = bv; outci[crow + t] = bid; }
    }
}

// ---------------------------------------------------------------------------
// merge NSPLIT x 16 candidates -> global top-16 per row. One warp per row.
// ---------------------------------------------------------------------------
__global__ void knnmerge_kernel(const float* __restrict__ cv, const int* __restrict__ ci,
                                int* __restrict__ outidx) {
    const int row = blockIdx.x * (blockDim.x >> 5) + (threadIdx.x >> 5);
    const int lane = threadIdx.x & 31;
    float v = cv[(long long)row * 32 + lane];
    int id = ci[(long long)row * 32 + lane];
    int rank = 0;
#pragma unroll
    for (int o = 0; o < 32; o++) {
        float ov = __shfl_sync(0xffffffffu, v, o);
        int oid = __shfl_sync(0xffffffffu, id, o);
        if (ov > v || (ov == v && oid < id)) rank++;
    }
    if (rank < KNN) outidx[(long long)row * KNN + rank] = id;
}

// ---------------------------------------------------------------------------
// SGEMM 64x64x16, 256 threads, 4x4 micro-tile in f32x2, double-buffered.
// ---------------------------------------------------------------------------
__global__ void sgemm_kernel(const float* __restrict__ A, int lda,
                             const float* __restrict__ W, int K, int D, int dual,
                             float* __restrict__ Co, int ldc,
                             const float* __restrict__ bg, const float* __restrict__ bb,
                             const float* __restrict__ bm, const float* __restrict__ bvv) {
    __shared__ float As[2][16 * 136];
    __shared__ float Bs[2][16 * 68];
    const int mb = blockIdx.y * 64, nb = blockIdx.x * 64;
    const int tid = threadIdx.x;
    const int ry = tid >> 4, rx = tid & 15;
    u64 acc[4][2];
#pragma unroll
    for (int r = 0; r < 4; r++) { acc[r][0] = 0ull; acc[r][1] = 0ull; }
    float ra[4], rb[4];

#pragma unroll
    for (int u = 0; u < 4; u++) {
        int t = tid + u * 256; int m = t >> 4, k = t & 15;
        ra[u] = (k < K) ? A[(long long)(mb + m) * lda + k] : 0.f;
    }
#pragma unroll
    for (int u = 0; u < 4; u++) {
        int t = tid + u * 256; int k = t >> 6, n = t & 63;
        int gn = nb + n;
        float val = 0.f;
        if (k < K) {
            if (!dual) val = W[(long long)k * D + gn];
            else if (gn < D) val = W[(long long)k * D + gn];
            else val = W[(long long)(K + k) * D + gn - D];
        }
        rb[u] = val;
    }
#pragma unroll
    for (int u = 0; u < 4; u++) {
        int t = tid + u * 256;
        As[0][(t & 15) * 136 + 2 * (t >> 4)] = ra[u];
        As[0][(t & 15) * 136 + 2 * (t >> 4) + 1] = ra[u];
        Bs[0][(t >> 6) * 68 + (t & 63)] = rb[u];
    }
    __syncthreads();

    int p = 0;
    for (int kt = 0; kt < K; kt += 16) {
        const bool more = (kt + 16 < K);
        if (more) {
#pragma unroll
            for (int u = 0; u < 4; u++) {
                int t = tid + u * 256; int m = t >> 4, k = kt + 16 + (t & 15);
                ra[u] = (k < K) ? A[(long long)(mb + m) * lda + k] : 0.f;
            }
#pragma unroll
            for (int u = 0; u < 4; u++) {
                int t = tid + u * 256; int k = kt + 16 + (t >> 6), n = t & 63;
                int gn = nb + n;
                float val = 0.f;
                if (k < K) {
                    if (!dual) val = W[(long long)k * D + gn];
                    else if (gn < D) val = W[(long long)k * D + gn];
                    else val = W[(long long)(K + k) * D + gn - D];
                }
                rb[u] = val;
            }
        }
#pragma unroll
        for (int k = 0; k < 16; k++) {
            ulonglong2 a01 = *(const ulonglong2*)&As[p][k * 136 + ry * 8];
            ulonglong2 a23 = *(const ulonglong2*)&As[p][k * 136 + ry * 8 + 4];
            ulonglong2 bq  = *(const ulonglong2*)&Bs[p][k * 68 + rx * 4];
            ffma2(acc[0][0], a01.x, bq.x); ffma2(acc[0][1], a01.x, bq.y);
            ffma2(acc[1][0], a01.y, bq.x); ffma2(acc[1][1], a01.y, bq.y);
            ffma2(acc[2][0], a23.x, bq.x); ffma2(acc[2][1], a23.x, bq.y);
            ffma2(acc[3][0], a23.y, bq.x); ffma2(acc[3][1], a23.y, bq.y);
        }
        if (more) {
            __syncthreads();
#pragma unroll
            for (int u = 0; u < 4; u++) {
                int t = tid + u * 256;
                As[p ^ 1][(t & 15) * 136 + 2 * (t >> 4)] = ra[u];
                As[p ^ 1][(t & 15) * 136 + 2 * (t >> 4) + 1] = ra[u];
                Bs[p ^ 1][(t >> 6) * 68 + (t & 63)] = rb[u];
            }
            __syncthreads();
            p ^= 1;
        }
    }

    float out[4][4];
#pragma unroll
    for (int i = 0; i < 4; i++) {
        float2 lo = unpack2(acc[i][0]);
        float2 hi = unpack2(acc[i][1]);
        out[i][0] = lo.x; out[i][1] = lo.y; out[i][2] = hi.x; out[i][3] = hi.y;
    }
    if (bg) {
#pragma unroll
        for (int j = 0; j < 4; j++) {
            int n = nb + rx * 4 + j;
            float s = bg[n] * rsqrtf(bvv[n] + BN_EPS);
            float t = bb[n] - bm[n] * s;
#pragma unroll
            for (int i = 0; i < 4; i++) out[i][j] = fmaxf(fmaf(out[i][j], s, t), 0.f);
        }
    }
#pragma unroll
    for (int i = 0; i < 4; i++) {
        *(float4*)&Co[(long long)(mb + ry * 4 + i) * ldc + nb + rx * 4] =
            make_float4(out[i][0], out[i][1], out[i][2], out[i][3]);
    }
}

// ---------------------------------------------------------------------------
// gather + BN + ReLU + max over k=16; fused next-stage sqnorm. Warp per row.
// ---------------------------------------------------------------------------
__global__ void gathermax_kernel(const float* __restrict__ ytb, const int* __restrict__ idx,
                                 int D,
                                 const float* __restrict__ g, const float* __restrict__ b,
                                 const float* __restrict__ m, const float* __restrict__ vv,
                                 float* __restrict__ out, float* __restrict__ sqout) {
    const int warp = (blockIdx.x * blockDim.x + threadIdx.x) >> 5;
    const int lane = threadIdx.x & 31;
    if (warp >= NROWS) return;
    const int row = warp;
    const int base = row & ~(NPTS - 1);
    const int myid = idx[(long long)row * KNN + (lane & 15)];
    const float* top = ytb + (long long)row * 2 * D;
    float ss = 0.f;
    for (int c0 = 0; c0 < D; c0 += 64) {
        const int d = c0 + lane * 2;
        float2 g2 = *(const float2*)&g[d];
        float2 v2 = *(const float2*)&vv[d];
        float2 b2 = *(const float2*)&b[d];
        float2 m2 = *(const float2*)&m[d];
        float sx = g2.x * rsqrtf(v2.x + BN_EPS), txx = b2.x - m2.x * sx;
        float sy = g2.y * rsqrtf(v2.y + BN_EPS), tyy = b2.y - m2.y * sy;
        float2 tp = *(const float2*)&top[d];
        float bx = -CUDART_INF_F, by = -CUDART_INF_F;
#pragma unroll
        for (int k = 0; k < KNN; k++) {
            int sk = __shfl_sync(0xffffffffu, myid, k, 16);
            float2 yb = *(const float2*)&ytb[(long long)(base + sk) * 2 * D + D + d];
            bx = fmaxf(bx, fmaf(tp.x + yb.x, sx, txx));
            by = fmaxf(by, fmaf(tp.y + yb.y, sy, tyy));
        }
        bx = fmaxf(bx, 0.f); by = fmaxf(by, 0.f);
        *(float2*)&out[(long long)row * 512 + d] = make_float2(bx, by);
        ss += bx * bx + by * by;
    }
#pragma unroll
    for (int off = 16; off > 0; off >>= 1) ss += __shfl_down_sync(0xffffffffu, ss, off);
    if (lane == 0) sqout[row] = ss;
}

// ---------------------------------------------------------------------------
template <int C>
static void launch_knn(const float* in, int lda, const float* sqp,
                       float* cvp, int* cip, int* idxp) {
    constexpr int BUFROWS = (C > 64) ? C : 64;
    size_t smem = (size_t)(C * 136 + BUFROWS * 68) * 4;
    static bool done = false;
    if (!done) {
        cudaFuncSetAttribute(knn_kernel<C>, cudaFuncAttributeMaxDynamicSharedMemorySize,
                             (int)smem);
        done = true;
    }
    knn_kernel<C><<<dim3(NPTS / 64, NBATCH, NSPLIT), 256, smem>>>(in, lda, sqp, cvp, cip);
    knnmerge_kernel<<<NROWS / 8, 256>>>(cvp, cip, idxp);
}

extern "C" void kernel_launch(void* const* d_in, const int* in_sizes, int n_in,
                              void* d_out, int out_size) {
    const float* x = (const float*)d_in[0];
    const float *W[5], *gg[5], *bb[5], *mm[5], *vv[5];
    for (int i = 0; i < 5; i++) {
        W[i]  = (const float*)d_in[1 + 5 * i];
        gg[i] = (const float*)d_in[2 + 5 * i];
        bb[i] = (const float*)d_in[3 + 5 * i];
        mm[i] = (const float*)d_in[4 + 5 * i];
        vv[i] = (const float*)d_in[5 + 5 * i];
    }
    float *xcat, *ytb, *sqp, *cvp; int *idxp, *cip;
    cudaGetSymbolAddress((void**)&xcat, g_xcat);
    cudaGetSymbolAddress((void**)&ytb, g_ytb);
    cudaGetSymbolAddress((void**)&sqp, g_sq);
    cudaGetSymbolAddress((void**)&idxp, g_idx);
    cudaGetSymbolAddress((void**)&cvp, g_cv);
    cudaGetSymbolAddress((void**)&cip, g_ci);

    const int Cs[4] = {3, 64, 64, 128};
    const int Ds[4] = {64, 64, 128, 256};

    sqnorm_kernel<<<NROWS / 256, 256>>>(x, 3, 3, sqp);

    const float* in = x;
    int lda = 3;
    int coloff = 0;
    for (int s = 0; s < 4; s++) {
        const int C = Cs[s], D = Ds[s];
        if (C == 3)        launch_knn<3>(in, lda, sqp, cvp, cip, idxp);
        else if (C == 64)  launch_knn<64>(in, lda, sqp, cvp, cip, idxp);
        else               launch_knn<128>(in, lda, sqp, cvp, cip, idxp);
        sgemm_kernel<<<dim3(2 * D / 64, NROWS / 64), 256>>>(in, lda, W[s], C, D, 1,
                                                            ytb, 2 * D,
                                                            nullptr, nullptr, nullptr, nullptr);
        float* outp = xcat + coloff;
        gathermax_kernel<<<NROWS / 8, 256>>>(ytb, idxp, D, gg[s], bb[s], mm[s], vv[s],
                                             outp, sqp);
        in = outp; lda = 512;
        coloff += D;
    }
    sgemm_kernel<<<dim3(512 / 64, NROWS / 64), 256>>>(xcat, 512, W[4], 512, 512, 0,
                                                      (float*)d_out, 512,
                                                      gg[4], bb[4], mm[4], vv[4]);
}

// round 10
// speedup vs baseline: 1.0152x; 1.0152x over previous
#include <cuda_runtime.h>
#include <math_constants.h>

#define BN_EPS 1e-3f
#define NPTS 2048
#define NBATCH 8
#define NROWS (NPTS * NBATCH)
#define KNN 16
#define NSPLIT 2

typedef unsigned long long u64;

__device__ float g_xcat[NROWS * 512];
__device__ float g_ytb[NROWS * 512];
__device__ float g_sq[NROWS];
__device__ int   g_idx[NROWS * KNN];
__device__ float g_cv[NROWS * KNN * NSPLIT];
__device__ int   g_ci[NROWS * KNN * NSPLIT];

// ---------------- f32x2 packed helpers (FFMA2: 2x fp32 throughput) ----------
__device__ __forceinline__ void ffma2(u64& d, u64 a, u64 b) {
    asm("fma.rn.f32x2 %0, %1, %2, %0;" : "+l"(d) : "l"(a), "l"(b));
}
__device__ __forceinline__ float2 unpack2(u64 v) {
    float2 r;
    asm("mov.b64 {%0, %1}, %2;" : "=f"(r.x), "=f"(r.y) : "l"(v));
    return r;
}

// ---------------------------------------------------------------------------
__global__ void sqnorm_kernel(const float* __restrict__ x, int lda, int C,
                              float* __restrict__ sq) {
    int i = blockIdx.x * blockDim.x + threadIdx.x;
    if (i < NROWS) {
        const float* p = x + (long long)i * lda;
        float s = 0.f;
        for (int c = 0; c < C; c++) { float v = p[c]; s = fmaf(v, v, s); }
        sq[i] = s;
    }
}

// ---------------------------------------------------------------------------
__device__ __forceinline__ void topk_ins(float (&v)[16], int (&id)[16],
                                         float& vmin, int& vminid, int& minpos,
                                         float pv, int jg) {
    if (pv > vmin || (pv == vmin && jg < vminid)) {
#pragma unroll
        for (int q = 0; q < 16; q++)
            if (q == minpos) { v[q] = pv; id[q] = jg; }
        vmin = v[0]; vminid = id[0]; minpos = 0;
#pragma unroll
        for (int q = 1; q < 16; q++) {
            bool w = (v[q] < vmin) || (v[q] == vmin && id[q] > vminid);
            if (w) { vmin = v[q]; vminid = id[q]; minpos = q; }
        }
    }
}

// ---------------------------------------------------------------------------
// kNN (split, pipelined): 64 i-rows x (NPTS/NSPLIT) j-range per block.
// 64-j tiles, c chunked by CC=32, DOUBLE-BUFFERED xjT with register prefetch:
// next chunk's LDGs fly while current chunk's FFMA2s issue (no serial load
// phase). 4x4 micro-tile in f32x2; top-16 per row with pre-max gating.
// ---------------------------------------------------------------------------
template <int C>
__global__ void knn_kernel(const float* __restrict__ x, int lda,
                           const float* __restrict__ sq,
                           float* __restrict__ outcv, int* __restrict__ outci) {
    constexpr int CC = (C < 32) ? C : 32;
    constexpr int NCHT = C / CC;                  // chunks per tile: 1,2,4
    constexpr int NREG = (64 * CC + 255) / 256;   // prefetch regs: 1 or 8
    constexpr int NTILES = NPTS / NSPLIT / 64;    // 16
    constexpr int Q = NTILES * NCHT;
    constexpr bool EXACT = ((64 * CC) % 256) == 0;

    extern __shared__ float sm[];
    float* xiD = sm;                         // C x 136 (dup (v,v) pairs)
    float* xjT = sm + C * 136;               // 2 x (CC x 68) double buffer
    float* pd  = xjT + 2 * CC * 68;          // 64 x 68

    const int rowbase = blockIdx.y * NPTS;
    const int i0 = blockIdx.x * 64;
    const int spbase = blockIdx.z * (NPTS / NSPLIT);
    const int tid = threadIdx.x;
    const int ty = tid >> 4, tx = tid & 15;
    const int srow = tid >> 2, sq4 = tid & 3;

    for (int t = tid; t < 64 * C; t += 256) {
        int i = t / C, c = t - i * C;
        float val = x[(long long)(rowbase + i0 + i) * lda + c];
        xiD[c * 136 + 2 * i] = val;
        xiD[c * 136 + 2 * i + 1] = val;
    }
    float sqi[4];
#pragma unroll
    for (int r = 0; r < 4; r++) sqi[r] = sq[rowbase + i0 + ty * 4 + r];

    float v[16]; int id[16];
#pragma unroll
    for (int q = 0; q < 16; q++) { v[q] = -CUDART_INF_F; id[q] = 0x7fffffff; }
    float vmin = -CUDART_INF_F; int vminid = 0x7fffffff; int minpos = 0;

    const float* xjp0 = xjT + tx * 4;

    float rx[NREG];
    // prologue: load + store chunk 0 into buffer 0
#pragma unroll
    for (int u = 0; u < NREG; u++) {
        int t = tid + u * 256;
        if (EXACT || t < 64 * CC)
            rx[u] = x[(long long)(rowbase + spbase + t / CC) * lda + t % CC];
    }
#pragma unroll
    for (int u = 0; u < NREG; u++) {
        int t = tid + u * 256;
        if (EXACT || t < 64 * CC)
            xjT[(t % CC) * 68 + t / CC] = rx[u];
    }
    __syncthreads();

    u64 acc[4][2];
#pragma unroll
    for (int r = 0; r < 4; r++) { acc[r][0] = 0ull; acc[r][1] = 0ull; }

    for (int q = 0; q < Q; q++) {
        const int ch = q % NCHT;
        const int jt = q / NCHT;
        const int j0 = spbase + jt * 64;
        const float* bufp = xjp0 + (q & 1) * CC * 68;

        // prefetch chunk q+1 into registers (LDGs overlap compute below)
        if (q + 1 < Q) {
            const int njt = (q + 1) / NCHT;
            const int ncb = ((q + 1) % NCHT) * CC;
            const int nj0 = spbase + njt * 64;
#pragma unroll
            for (int u = 0; u < NREG; u++) {
                int t = tid + u * 256;
                if (EXACT || t < 64 * CC)
                    rx[u] = x[(long long)(rowbase + nj0 + t / CC) * lda + ncb + t % CC];
            }
        }

        // compute chunk q
        const float* xip = xiD + (ch * CC) * 136 + ty * 8;
#pragma unroll 4
        for (int c = 0; c < CC; c++) {
            ulonglong2 a01 = *(const ulonglong2*)(xip + c * 136);
            ulonglong2 a23 = *(const ulonglong2*)(xip + c * 136 + 4);
            ulonglong2 bq  = *(const ulonglong2*)(bufp + c * 68);
            ffma2(acc[0][0], a01.x, bq.x); ffma2(acc[0][1], a01.x, bq.y);
            ffma2(acc[1][0], a01.y, bq.x); ffma2(acc[1][1], a01.y, bq.y);
            ffma2(acc[2][0], a23.x, bq.x); ffma2(acc[2][1], a23.x, bq.y);
            ffma2(acc[3][0], a23.y, bq.x); ffma2(acc[3][1], a23.y, bq.y);
        }

        if (ch == NCHT - 1) {
            // epilogue: pd = 2*dot - sqi - sqj -> pd buffer
            float4 sj = *(const float4*)&sq[rowbase + j0 + tx * 4];
#pragma unroll
            for (int r = 0; r < 4; r++) {
                float2 lo = unpack2(acc[r][0]);
                float2 hi = unpack2(acc[r][1]);
                float4 o;
                o.x = 2.f * lo.x - sqi[r] - sj.x;
                o.y = 2.f * lo.y - sqi[r] - sj.y;
                o.z = 2.f * hi.x - sqi[r] - sj.z;
                o.w = 2.f * hi.y - sqi[r] - sj.w;
                *(float4*)&pd[(ty * 4 + r) * 68 + tx * 4] = o;
                acc[r][0] = 0ull; acc[r][1] = 0ull;
            }
        }
        __syncthreads();   // buf[q&1] reads done; pd visible

        // store prefetched chunk into the other buffer
        if (q + 1 < Q) {
#pragma unroll
            for (int u = 0; u < NREG; u++) {
                int t = tid + u * 256;
                if (EXACT || t < 64 * CC)
                    xjT[((q + 1) & 1) * CC * 68 + (t % CC) * 68 + t / CC] = rx[u];
            }
        }

        if (ch == NCHT - 1) {
            // selection: thread (srow, sq4) scans j strip, pre-max gated
            float tmax = -CUDART_INF_F;
#pragma unroll
            for (int s = 0; s < 4; s++) {
                const float4 pv = *(const float4*)&pd[srow * 68 + sq4 * 16 + s * 4];
                tmax = fmaxf(tmax, fmaxf(fmaxf(pv.x, pv.y), fmaxf(pv.z, pv.w)));
            }
            if (tmax >= vmin) {
#pragma unroll
                for (int s = 0; s < 4; s++) {
                    const float4 pv = *(const float4*)&pd[srow * 68 + sq4 * 16 + s * 4];
                    float m4 = fmaxf(fmaxf(pv.x, pv.y), fmaxf(pv.z, pv.w));
                    if (m4 >= vmin) {
                        int jb = j0 + sq4 * 16 + s * 4;
                        topk_ins(v, id, vmin, vminid, minpos, pv.x, jb);
                        topk_ins(v, id, vmin, vminid, minpos, pv.y, jb + 1);
                        topk_ins(v, id, vmin, vminid, minpos, pv.z, jb + 2);
                        topk_ins(v, id, vmin, vminid, minpos, pv.w, jb + 3);
                    }
                }
            }
        }
        __syncthreads();   // new buffer contents visible for chunk q+1
    }

    // merge 4 lanes x 16 entries -> top-16 per row via warp shuffles
    const long long crow = (long long)(rowbase + i0 + srow) * (KNN * NSPLIT)
                           + blockIdx.z * KNN;
    for (int t = 0; t < KNN; t++) {
        float bv = -CUDART_INF_F; int bid = 0x7fffffff; int bq = 0;
#pragma unroll
        for (int q = 0; q < 16; q++) {
            bool w = (v[q] > bv) || (v[q] == bv && id[q] < bid);
            if (w) { bv = v[q]; bid = id[q]; bq = q; }
        }
        float lv = bv; int lid = bid;
#pragma unroll
        for (int off = 1; off < 4; off <<= 1) {
            float ov = __shfl_xor_sync(0xffffffffu, bv, off);
            int oid = __shfl_xor_sync(0xffffffffu, bid, off);
            if (ov > bv || (ov == bv && oid < bid)) { bv = ov; bid = oid; }
        }
        if (lid == bid && lv == bv) { v[bq] = -CUDART_INF_F; id[bq] = 0x7fffffff; }
        if (sq4 == 0) { outcv[crow + t] = bv; outci[crow + t] = bid; }
    }
}

// ---------------------------------------------------------------------------
// merge NSPLIT x 16 candidates -> global top-16 per row. One warp per row.
// ---------------------------------------------------------------------------
__global__ void knnmerge_kernel(const float* __restrict__ cv, const int* __restrict__ ci,
                                int* __restrict__ outidx) {
    const int row = blockIdx.x * (blockDim.x >> 5) + (threadIdx.x >> 5);
    const int lane = threadIdx.x & 31;
    float v = cv[(long long)row * 32 + lane];
    int id = ci[(long long)row * 32 + lane];
    int rank = 0;
#pragma unroll
    for (int o = 0; o < 32; o++) {
        float ov = __shfl_sync(0xffffffffu, v, o);
        int oid = __shfl_sync(0xffffffffu, id, o);
        if (ov > v || (ov == v && oid < id)) rank++;
    }
    if (rank < KNN) outidx[(long long)row * KNN + rank] = id;
}

// ---------------------------------------------------------------------------
// SGEMM 64x64x16, 256 threads, 4x4 micro-tile in f32x2, double-buffered.
// ---------------------------------------------------------------------------
__global__ void sgemm_kernel(const float* __restrict__ A, int lda,
                             const float* __restrict__ W, int K, int D, int dual,
                             float* __restrict__ Co, int ldc,
                             const float* __restrict__ bg, const float* __restrict__ bb,
                             const float* __restrict__ bm, const float* __restrict__ bvv) {
    __shared__ float As[2][16 * 136];
    __shared__ float Bs[2][16 * 68];
    const int mb = blockIdx.y * 64, nb = blockIdx.x * 64;
    const int tid = threadIdx.x;
    const int ry = tid >> 4, rx = tid & 15;
    u64 acc[4][2];
#pragma unroll
    for (int r = 0; r < 4; r++) { acc[r][0] = 0ull; acc[r][1] = 0ull; }
    float ra[4], rb[4];

#pragma unroll
    for (int u = 0; u < 4; u++) {
        int t = tid + u * 256; int m = t >> 4, k = t & 15;
        ra[u] = (k < K) ? A[(long long)(mb + m) * lda + k] : 0.f;
    }
#pragma unroll
    for (int u = 0; u < 4; u++) {
        int t = tid + u * 256; int k = t >> 6, n = t & 63;
        int gn = nb + n;
        float val = 0.f;
        if (k < K) {
            if (!dual) val = W[(long long)k * D + gn];
            else if (gn < D) val = W[(long long)k * D + gn];
            else val = W[(long long)(K + k) * D + gn - D];
        }
        rb[u] = val;
    }
#pragma unroll
    for (int u = 0; u < 4; u++) {
        int t = tid + u * 256;
        As[0][(t & 15) * 136 + 2 * (t >> 4)] = ra[u];
        As[0][(t & 15) * 136 + 2 * (t >> 4) + 1] = ra[u];
        Bs[0][(t >> 6) * 68 + (t & 63)] = rb[u];
    }
    __syncthreads();

    int p = 0;
    for (int kt = 0; kt < K; kt += 16) {
        const bool more = (kt + 16 < K);
        if (more) {
#pragma unroll
            for (int u = 0; u < 4; u++) {
                int t = tid + u * 256; int m = t >> 4, k = kt + 16 + (t & 15);
                ra[u] = (k < K) ? A[(long long)(mb + m) * lda + k] : 0.f;
            }
#pragma unroll
            for (int u = 0; u < 4; u++) {
                int t = tid + u * 256; int k = kt + 16 + (t >> 6), n = t & 63;
                int gn = nb + n;
                float val = 0.f;
                if (k < K) {
                    if (!dual) val = W[(long long)k * D + gn];
                    else if (gn < D) val = W[(long long)k * D + gn];
                    else val = W[(long long)(K + k) * D + gn - D];
                }
                rb[u] = val;
            }
        }
#pragma unroll
        for (int k = 0; k < 16; k++) {
            ulonglong2 a01 = *(const ulonglong2*)&As[p][k * 136 + ry * 8];
            ulonglong2 a23 = *(const ulonglong2*)&As[p][k * 136 + ry * 8 + 4];
            ulonglong2 bq  = *(const ulonglong2*)&Bs[p][k * 68 + rx * 4];
            ffma2(acc[0][0], a01.x, bq.x); ffma2(acc[0][1], a01.x, bq.y);
            ffma2(acc[1][0], a01.y, bq.x); ffma2(acc[1][1], a01.y, bq.y);
            ffma2(acc[2][0], a23.x, bq.x); ffma2(acc[2][1], a23.x, bq.y);
            ffma2(acc[3][0], a23.y, bq.x); ffma2(acc[3][1], a23.y, bq.y);
        }
        if (more) {
            __syncthreads();
#pragma unroll
            for (int u = 0; u < 4; u++) {
                int t = tid + u * 256;
                As[p ^ 1][(t & 15) * 136 + 2 * (t >> 4)] = ra[u];
                As[p ^ 1][(t & 15) * 136 + 2 * (t >> 4) + 1] = ra[u];
                Bs[p ^ 1][(t >> 6) * 68 + (t & 63)] = rb[u];
            }
            __syncthreads();
            p ^= 1;
        }
    }

    float out[4][4];
#pragma unroll
    for (int i = 0; i < 4; i++) {
        float2 lo = unpack2(acc[i][0]);
        float2 hi = unpack2(acc[i][1]);
        out[i][0] = lo.x; out[i][1] = lo.y; out[i][2] = hi.x; out[i][3] = hi.y;
    }
    if (bg) {
#pragma unroll
        for (int j = 0; j < 4; j++) {
            int n = nb + rx * 4 + j;
            float s = bg[n] * rsqrtf(bvv[n] + BN_EPS);
            float t = bb[n] - bm[n] * s;
#pragma unroll
            for (int i = 0; i < 4; i++) out[i][j] = fmaxf(fmaf(out[i][j], s, t), 0.f);
        }
    }
#pragma unroll
    for (int i = 0; i < 4; i++) {
        *(float4*)&Co[(long long)(mb + ry * 4 + i) * ldc + nb + rx * 4] =
            make_float4(out[i][0], out[i][1], out[i][2], out[i][3]);
    }
}

// ---------------------------------------------------------------------------
// gather + BN + ReLU + max over k=16; fused next-stage sqnorm. Warp per row.
// ---------------------------------------------------------------------------
__global__ void gathermax_kernel(const float* __restrict__ ytb, const int* __restrict__ idx,
                                 int D,
                                 const float* __restrict__ g, const float* __restrict__ b,
                                 const float* __restrict__ m, const float* __restrict__ vv,
                                 float* __restrict__ out, float* __restrict__ sqout) {
    const int warp = (blockIdx.x * blockDim.x + threadIdx.x) >> 5;
    const int lane = threadIdx.x & 31;
    if (warp >= NROWS) return;
    const int row = warp;
    const int base = row & ~(NPTS - 1);
    const int myid = idx[(long long)row * KNN + (lane & 15)];
    const float* top = ytb + (long long)row * 2 * D;
    float ss = 0.f;
    for (int c0 = 0; c0 < D; c0 += 64) {
        const int d = c0 + lane * 2;
        float2 g2 = *(const float2*)&g[d];
        float2 v2 = *(const float2*)&vv[d];
        float2 b2 = *(const float2*)&b[d];
        float2 m2 = *(const float2*)&m[d];
        float sx = g2.x * rsqrtf(v2.x + BN_EPS), txx = b2.x - m2.x * sx;
        float sy = g2.y * rsqrtf(v2.y + BN_EPS), tyy = b2.y - m2.y * sy;
        float2 tp = *(const float2*)&top[d];
        float bx = -CUDART_INF_F, by = -CUDART_INF_F;
#pragma unroll
        for (int k = 0; k < KNN; k++) {
            int sk = __shfl_sync(0xffffffffu, myid, k, 16);
            float2 yb = *(const float2*)&ytb[(long long)(base + sk) * 2 * D + D + d];
            bx = fmaxf(bx, fmaf(tp.x + yb.x, sx, txx));
            by = fmaxf(by, fmaf(tp.y + yb.y, sy, tyy));
        }
        bx = fmaxf(bx, 0.f); by = fmaxf(by, 0.f);
        *(float2*)&out[(long long)row * 512 + d] = make_float2(bx, by);
        ss += bx * bx + by * by;
    }
#pragma unroll
    for (int off = 16; off > 0; off >>= 1) ss += __shfl_down_sync(0xffffffffu, ss, off);
    if (lane == 0) sqout[row] = ss;
}

// ---------------------------------------------------------------------------
template <int C>
static void launch_knn(const float* in, int lda, const float* sqp,
                       float* cvp, int* cip, int* idxp) {
    constexpr int CC = (C < 32) ? C : 32;
    size_t smem = (size_t)(C * 136 + 2 * CC * 68 + 64 * 68) * 4;
    static bool done = false;
    if (!done) {
        cudaFuncSetAttribute(knn_kernel<C>, cudaFuncAttributeMaxDynamicSharedMemorySize,
                             (int)smem);
        done = true;
    }
    knn_kernel<C><<<dim3(NPTS / 64, NBATCH, NSPLIT), 256, smem>>>(in, lda, sqp, cvp, cip);
    knnmerge_kernel<<<NROWS / 8, 256>>>(cvp, cip, idxp);
}

extern "C" void kernel_launch(void* const* d_in, const int* in_sizes, int n_in,
                              void* d_out, int out_size) {
    const float* x = (const float*)d_in[0];
    const float *W[5], *gg[5], *bb[5], *mm[5], *vv[5];
    for (int i = 0; i < 5; i++) {
        W[i]  = (const float*)d_in[1 + 5 * i];
        gg[i] = (const float*)d_in[2 + 5 * i];
        bb[i] = (const float*)d_in[3 + 5 * i];
        mm[i] = (const float*)d_in[4 + 5 * i];
        vv[i] = (const float*)d_in[5 + 5 * i];
    }
    float *xcat, *ytb, *sqp, *cvp; int *idxp, *cip;
    cudaGetSymbolAddress((void**)&xcat, g_xcat);
    cudaGetSymbolAddress((void**)&ytb, g_ytb);
    cudaGetSymbolAddress((void**)&sqp, g_sq);
    cudaGetSymbolAddress((void**)&idxp, g_idx);
    cudaGetSymbolAddress((void**)&cvp, g_cv);
    cudaGetSymbolAddress((void**)&cip, g_ci);

    const int Cs[4] = {3, 64, 64, 128};
    const int Ds[4] = {64, 64, 128, 256};

    sqnorm_kernel<<<NROWS / 256, 256>>>(x, 3, 3, sqp);

    const float* in = x;
    int lda = 3;
    int coloff = 0;
    for (int s = 0; s < 4; s++) {
        const int C = Cs[s], D = Ds[s];
        if (C == 3)        launch_knn<3>(in, lda, sqp, cvp, cip, idxp);
        else if (C == 64)  launch_knn<64>(in, lda, sqp, cvp, cip, idxp);
        else               launch_knn<128>(in, lda, sqp, cvp, cip, idxp);
        sgemm_kernel<<<dim3(2 * D / 64, NROWS / 64), 256>>>(in, lda, W[s], C, D, 1,
                                                            ytb, 2 * D,
                                                            nullptr, nullptr, nullptr, nullptr);
        float* outp = xcat + coloff;
        gathermax_kernel<<<NROWS / 8, 256>>>(ytb, idxp, D, gg[s], bb[s], mm[s], vv[s],
                                             outp, sqp);
        in = outp; lda = 512;
        coloff += D;
    }
    sgemm_kernel<<<dim3(512 / 64, NROWS / 64), 256>>>(xcat, 512, W[4], 512, 512, 0,
                                                      (float*)d_out, 512,
                                                      gg[4], bb[4], mm[4], vv[4]);
}